// round 9
// baseline (speedup 1.0000x reference)
#include <cuda_runtime.h>
#include <cuda_bf16.h>
#include <cstdint>

// ======================= problem constants =======================
#define BATCH 64
#define WDIM  513
#define CDIM  512
#define PLANE_ELEMS (BATCH * WDIM * CDIM)   // 16,809,984

// bf16 hi/lo planes of the L2-normalized inputs (scratch, ~134 MB)
__device__ __nv_bfloat16 g_h1[PLANE_ELEMS];
__device__ __nv_bfloat16 g_l1[PLANE_ELEMS];
__device__ __nv_bfloat16 g_h2[PLANE_ELEMS];
__device__ __nv_bfloat16 g_l2[PLANE_ELEMS];
// inverse L2 norms per (b, c)
__device__ float g_inv1[BATCH * CDIM];
__device__ float g_inv2[BATCH * CDIM];

// ======================= helpers =======================
__device__ __forceinline__ uint32_t smem_u32(const void* p) {
    uint32_t a;
    asm("{ .reg .u64 t; cvta.to.shared.u64 t, %1; cvt.u32.u64 %0, t; }" : "=r"(a) : "l"(p));
    return a;
}

#define CP_ASYNC16(dst, src) \
    asm volatile("cp.async.cg.shared.global [%0], [%1], 16;" :: "r"(dst), "l"(src) : "memory")
#define CP_COMMIT() asm volatile("cp.async.commit_group;" ::: "memory")
#define CP_WAIT(n)  asm volatile("cp.async.wait_group %0;" :: "n"(n) : "memory")

__device__ __forceinline__ void mma16816(float* d, uint32_t a0, uint32_t a1, uint32_t a2,
                                         uint32_t a3, uint32_t b0, uint32_t b1) {
    asm volatile(
        "mma.sync.aligned.m16n8k16.row.col.f32.bf16.bf16.f32 "
        "{%0,%1,%2,%3}, {%4,%5,%6,%7}, {%8,%9}, {%0,%1,%2,%3};"
        : "+f"(d[0]), "+f"(d[1]), "+f"(d[2]), "+f"(d[3])
        : "r"(a0), "r"(a1), "r"(a2), "r"(a3), "r"(b0), "r"(b1));
}

__device__ __forceinline__ void ldsm_x4(uint32_t* r, uint32_t addr) {
    asm volatile("ldmatrix.sync.aligned.m8n8.x4.shared.b16 {%0,%1,%2,%3}, [%4];"
                 : "=r"(r[0]), "=r"(r[1]), "=r"(r[2]), "=r"(r[3]) : "r"(addr));
}

// ======================= kernel 1: fused normalize + bf16 hi/lo split =======================
// grid (64, 2, 8): batch, tensor, 64-channel block. 256 threads = 32 channel-pairs x 8 W-slices.
__global__ void __launch_bounds__(256) prep_kernel(const float* __restrict__ x1,
                                                   const float* __restrict__ x2) {
    __shared__ float2 red[8][32];
    __shared__ float2 sinv[32];
    const int b = blockIdx.x, which = blockIdx.y, cb = blockIdx.z;
    const float* in = which ? x2 : x1;
    __nv_bfloat16* hp = which ? g_h2 : g_h1;
    __nv_bfloat16* lp = which ? g_l2 : g_l1;
    float* invp = which ? g_inv2 : g_inv1;

    const int cp = threadIdx.x & 31;          // channel pair within block
    const int sl = threadIdx.x >> 5;          // W slice (0..7)
    const int c  = (cb << 6) + (cp << 1);     // absolute channel (even)
    const int w0 = sl * 65;
    const int w1 = (w0 + 65 < WDIM) ? (w0 + 65) : WDIM;
    const size_t base = (size_t)b * WDIM * CDIM + c;

    float s0 = 0.0f, s1 = 0.0f;
    for (int w = w0; w < w1; ++w) {
        float2 v = *(const float2*)(in + base + (size_t)w * CDIM);
        s0 = fmaf(v.x, v.x, s0);
        s1 = fmaf(v.y, v.y, s1);
    }
    red[sl][cp] = make_float2(s0, s1);
    __syncthreads();
    if (threadIdx.x < 32) {
        float a0 = 0.0f, a1 = 0.0f;
#pragma unroll
        for (int s = 0; s < 8; ++s) { a0 += red[s][threadIdx.x].x; a1 += red[s][threadIdx.x].y; }
        float2 iv = make_float2(rsqrtf(fmaxf(a0, 1e-12f)), rsqrtf(fmaxf(a1, 1e-12f)));
        sinv[threadIdx.x] = iv;
        *(float2*)(invp + b * CDIM + (cb << 6) + (threadIdx.x << 1)) = iv;
    }
    __syncthreads();
    const float2 iv = sinv[cp];

    for (int w = w0; w < w1; ++w) {
        const size_t idx = base + (size_t)w * CDIM;
        float2 v = *(const float2*)(in + idx);
        v.x *= iv.x;
        v.y *= iv.y;
        __nv_bfloat162 h = __floats2bfloat162_rn(v.x, v.y);
        float2 hf = __bfloat1622float2(h);
        __nv_bfloat162 l = __floats2bfloat162_rn(v.x - hf.x, v.y - hf.y);
        *(__nv_bfloat162*)(hp + idx) = h;
        *(__nv_bfloat162*)(lp + idx) = l;
    }
}

// ======================= kernel 2: strips (j=512 row, w'=512 col); inits out =======================
__global__ void __launch_bounds__(512) strip_kernel(const float* __restrict__ x1,
                                                    const float* __restrict__ x2,
                                                    float* __restrict__ out) {
    __shared__ float p1[CDIM], p2[CDIM], acc[WDIM];
    const int b = blockIdx.x;
    const int tid = threadIdx.x;
    const int wid = tid >> 5, lane = tid & 31;

    {
        float iv = g_inv1[b * CDIM + tid] * g_inv2[b * CDIM + tid];
        p1[tid] = x1[((size_t)b * WDIM + 512) * CDIM + tid] * iv;  // x1n[512]·inv2
        p2[tid] = x2[((size_t)b * WDIM + 512) * CDIM + tid] * iv;  // x2n[512]·inv1
    }
    __syncthreads();

    // part 1: j = 512 fixed, all w':  out[(768-w') % 513] = <p1, x2[w',:]>  (covers every w once)
    for (int wp = wid; wp < WDIM; wp += 16) {
        const float4* row = (const float4*)(x2 + ((size_t)b * WDIM + wp) * CDIM);
        const float4* P   = (const float4*)p1;
        float s = 0.0f;
#pragma unroll
        for (int q = 0; q < 4; ++q) {
            float4 a  = row[lane + (q << 5)];
            float4 pv = P[lane + (q << 5)];
            s += a.x * pv.x + a.y * pv.y + a.z * pv.z + a.w * pv.w;
        }
        for (int o = 16; o; o >>= 1) s += __shfl_xor_sync(0xFFFFFFFFu, s, o);
        if (lane == 0) acc[(768 - wp) % WDIM] = s;
    }
    __syncthreads();

    // part 2: w' = 512 fixed, j in 0..511:  out[(j+257) % 513] += <p2, x1[j,:]>
    for (int j = wid; j < 512; j += 16) {
        const float4* row = (const float4*)(x1 + ((size_t)b * WDIM + j) * CDIM);
        const float4* P   = (const float4*)p2;
        float s = 0.0f;
#pragma unroll
        for (int q = 0; q < 4; ++q) {
            float4 a  = row[lane + (q << 5)];
            float4 pv = P[lane + (q << 5)];
            s += a.x * pv.x + a.y * pv.y + a.z * pv.z + a.w * pv.w;
        }
        for (int o = 16; o; o >>= 1) s += __shfl_xor_sync(0xFFFFFFFFu, s, o);
        if (lane == 0) acc[(j + 257) % WDIM] += s;
    }
    __syncthreads();

    for (int w = tid; w < WDIM; w += 512) out[(size_t)b * WDIM + w] = acc[w];
}

// ======================= kernel 3: mma.sync GEMM (64x64 warp tiles) ==========
// CTA: 128(M=j) x 128(N=w') Gram tile; K = 3 x 512 (hi·hi, lo·hi, hi·lo), chunk = 64 halves.
// 128 threads = 4 warps (2M x 2N), warp tile 64x64 -> smem-read per MAC cut 1.56x
// (per chunk per CTA: tensor 1024 cyc vs smem port 768 cyc -> tensor-bound).
#define NCHUNKS  24                    // 1536 / 64
#define STAGE    32768                 // A 16KB + B 16KB (128 rows x 128B each)
#define NSTAGE   3
#define CPITCH   130
#define SMEM_GEMM (NSTAGE * STAGE)     // 98304 >= epilogue 128*130*4 = 66560

__global__ void __launch_bounds__(128, 2) gemm_kernel(float* __restrict__ out) {
    extern __shared__ char sm[];
    const uint32_t sb = smem_u32(sm);

    const int tid  = threadIdx.x;
    const int lane = tid & 31, warp = tid >> 5;
    const int wm = warp >> 1, wn = warp & 1;       // warp grid 2(M) x 2(N)
    const int l15 = lane & 15;

    const int b  = blockIdx.x >> 4;
    const int j0 = ((blockIdx.x >> 2) & 3) << 7;
    const int n0 = (blockIdx.x & 3) << 7;

    float acc[4][8][4];
#pragma unroll
    for (int mt = 0; mt < 4; ++mt)
#pragma unroll
        for (int nt = 0; nt < 8; ++nt)
#pragma unroll
            for (int i = 0; i < 4; ++i) acc[mt][nt][i] = 0.0f;

    // O(1)-register loader bases: 128 threads cover 16 rows per q-step; row = lr + 16q
    // so (r & 7) — and the swizzle — stay q-invariant. dst += q*2048 B, src += q*16*CDIM.
    const int lr = tid >> 3, lc = tid & 7;
    const uint32_t dOff0 = (uint32_t)((lr << 7) + ((lc ^ (lr & 7)) << 4));
    const uint32_t sOff0 = (uint32_t)(lr * CDIM + (lc << 3));
    const size_t rowA = ((size_t)(b * WDIM + j0)) * CDIM + sOff0;
    const size_t rowB = ((size_t)(b * WDIM + n0)) * CDIM + sOff0;

    // per-lane ldmatrix address components (row base * 128B + swizzled 16B chunk)
    uint32_t offk[4];
#pragma unroll
    for (int ks = 0; ks < 4; ++ks)
        offk[ks] = (uint32_t)((((ks << 1) | (lane >> 4)) ^ (lane & 7)) << 4);
    uint32_t arow[4], brow[4];
#pragma unroll
    for (int mt = 0; mt < 4; ++mt) arow[mt] = (uint32_t)((wm * 64 + mt * 16 + l15) << 7);
#pragma unroll
    for (int ng = 0; ng < 4; ++ng) brow[ng] = (uint32_t)((wn * 64 + ng * 16 + l15) << 7);

    // async chunk loader: 64 halves of K (128B/row), XOR-swizzled 16B chunks
    auto load_chunk = [&](int k, int s) {
        const int seg = k >> 3;
        const uint32_t c0 = (k & 7) << 6;
        const __nv_bfloat16* pa = ((seg == 1) ? g_l1 : g_h1) + rowA + c0;
        const __nv_bfloat16* pb = ((seg == 2) ? g_l2 : g_h2) + rowB + c0;
        const uint32_t sA = sb + s * STAGE + dOff0;
        const uint32_t sB = sA + 16384;
#pragma unroll
        for (int q = 0; q < 8; ++q) CP_ASYNC16(sA + q * 2048, pa + q * (16 * CDIM));
#pragma unroll
        for (int q = 0; q < 8; ++q) CP_ASYNC16(sB + q * 2048, pb + q * (16 * CDIM));
        CP_COMMIT();
    };

    load_chunk(0, 0);
    load_chunk(1, 1);

    int st = 0, ls = 2;
    for (int k = 0; k < NCHUNKS; ++k) {
        if (k < NCHUNKS - 1) { CP_WAIT(1); } else { CP_WAIT(0); }
        __syncthreads();
        if (k + 2 < NCHUNKS) load_chunk(k + 2, ls);

        const uint32_t sA = sb + st * STAGE;
        const uint32_t sB = sA + 16384;
#pragma unroll
        for (int ks = 0; ks < 4; ++ks) {
            uint32_t a[16], q[16];
#pragma unroll
            for (int mt = 0; mt < 4; ++mt) ldsm_x4(a + 4 * mt, sA + arow[mt] + offk[ks]);
#pragma unroll
            for (int ng = 0; ng < 4; ++ng) ldsm_x4(q + 4 * ng, sB + brow[ng] + offk[ks]);
#pragma unroll
            for (int mt = 0; mt < 4; ++mt)
#pragma unroll
                for (int ng = 0; ng < 4; ++ng) {
                    mma16816(acc[mt][ng * 2],     a[4*mt], a[4*mt+1], a[4*mt+2], a[4*mt+3],
                             q[4*ng], q[4*ng+2]);
                    mma16816(acc[mt][ng * 2 + 1], a[4*mt], a[4*mt+1], a[4*mt+2], a[4*mt+3],
                             q[4*ng+1], q[4*ng+3]);
                }
        }
        st = (st == NSTAGE - 1) ? 0 : st + 1;
        ls = (ls == NSTAGE - 1) ? 0 : ls + 1;
    }

    // --- epilogue: stage C in smem, fold diagonals, atomicAdd to global ---
    __syncthreads();
    float* C = (float*)sm;
    const int g = lane >> 2, t4 = lane & 3;
#pragma unroll
    for (int mt = 0; mt < 4; ++mt) {
        const int r0 = wm * 64 + mt * 16 + g;
#pragma unroll
        for (int nt = 0; nt < 8; ++nt) {
            const int c = wn * 64 + nt * 8 + 2 * t4;
            C[r0 * CPITCH + c]           = acc[mt][nt][0];
            C[r0 * CPITCH + c + 1]       = acc[mt][nt][1];
            C[(r0 + 8) * CPITCH + c]     = acc[mt][nt][2];
            C[(r0 + 8) * CPITCH + c + 1] = acc[mt][nt][3];
        }
    }
    __syncthreads();

    for (int dd = tid; dd < 255; dd += 128) {
        const int d = dd - 127;                  // diag offset r - c
        float s = 0.0f;
#pragma unroll 4
        for (int r = 0; r < 128; ++r) {
            const int c = r - d;
            if (c >= 0 && c < 128) s += C[r * CPITCH + c];
        }
        const int widx = (j0 - n0 + d + 256 + 1026) % WDIM;
        atomicAdd(&out[(size_t)b * WDIM + widx], s);
    }
}

// ======================= launch =======================
extern "C" void kernel_launch(void* const* d_in, const int* in_sizes, int n_in,
                              void* d_out, int out_size) {
    const float* x1 = (const float*)d_in[0];
    const float* x2 = (const float*)d_in[1];
    float* out = (float*)d_out;

    cudaFuncSetAttribute(gemm_kernel, cudaFuncAttributeMaxDynamicSharedMemorySize, SMEM_GEMM);

    prep_kernel<<<dim3(BATCH, 2, 8), 256>>>(x1, x2);
    strip_kernel<<<BATCH, 512>>>(x1, x2, out);
    gemm_kernel<<<BATCH * 16, 128, SMEM_GEMM>>>(out);
}

// round 10
// speedup vs baseline: 1.6074x; 1.6074x over previous
#include <cuda_runtime.h>
#include <cuda_fp16.h>
#include <cstdint>

// ======================= problem constants =======================
#define BATCH 64
#define WDIM  513
#define CDIM  512
#define PLANE_ELEMS (BATCH * WDIM * CDIM)   // 16,809,984

// fp16 planes of the L2-normalized inputs (scratch, ~67 MB)
__device__ __half g_h1[PLANE_ELEMS];
__device__ __half g_h2[PLANE_ELEMS];
// inverse L2 norms per (b, c)
__device__ float g_inv1[BATCH * CDIM];
__device__ float g_inv2[BATCH * CDIM];

// ======================= helpers =======================
__device__ __forceinline__ uint32_t smem_u32(const void* p) {
    uint32_t a;
    asm("{ .reg .u64 t; cvta.to.shared.u64 t, %1; cvt.u32.u64 %0, t; }" : "=r"(a) : "l"(p));
    return a;
}

#define CP_ASYNC16(dst, src) \
    asm volatile("cp.async.cg.shared.global [%0], [%1], 16;" :: "r"(dst), "l"(src) : "memory")
#define CP_COMMIT() asm volatile("cp.async.commit_group;" ::: "memory")
#define CP_WAIT(n)  asm volatile("cp.async.wait_group %0;" :: "n"(n) : "memory")

__device__ __forceinline__ void mma16816(float* d, uint32_t a0, uint32_t a1, uint32_t a2,
                                         uint32_t a3, uint32_t b0, uint32_t b1) {
    asm volatile(
        "mma.sync.aligned.m16n8k16.row.col.f32.f16.f16.f32 "
        "{%0,%1,%2,%3}, {%4,%5,%6,%7}, {%8,%9}, {%0,%1,%2,%3};"
        : "+f"(d[0]), "+f"(d[1]), "+f"(d[2]), "+f"(d[3])
        : "r"(a0), "r"(a1), "r"(a2), "r"(a3), "r"(b0), "r"(b1));
}

__device__ __forceinline__ void ldsm_x4(uint32_t* r, uint32_t addr) {
    asm volatile("ldmatrix.sync.aligned.m8n8.x4.shared.b16 {%0,%1,%2,%3}, [%4];"
                 : "=r"(r[0]), "=r"(r[1]), "=r"(r[2]), "=r"(r[3]) : "r"(addr));
}

// ======================= kernel 1: fused normalize + fp16 quantize =======================
// grid (64, 2, 8): batch, tensor, 64-channel block. 256 threads = 32 channel-pairs x 8 W-slices.
__global__ void __launch_bounds__(256) prep_kernel(const float* __restrict__ x1,
                                                   const float* __restrict__ x2) {
    __shared__ float2 red[8][32];
    __shared__ float2 sinv[32];
    const int b = blockIdx.x, which = blockIdx.y, cb = blockIdx.z;
    const float* in = which ? x2 : x1;
    __half* hp = which ? g_h2 : g_h1;
    float* invp = which ? g_inv2 : g_inv1;

    const int cp = threadIdx.x & 31;          // channel pair within block
    const int sl = threadIdx.x >> 5;          // W slice (0..7)
    const int c  = (cb << 6) + (cp << 1);     // absolute channel (even)
    const int w0 = sl * 65;
    const int w1 = (w0 + 65 < WDIM) ? (w0 + 65) : WDIM;
    const size_t base = (size_t)b * WDIM * CDIM + c;

    float s0 = 0.0f, s1 = 0.0f;
    for (int w = w0; w < w1; ++w) {
        float2 v = *(const float2*)(in + base + (size_t)w * CDIM);
        s0 = fmaf(v.x, v.x, s0);
        s1 = fmaf(v.y, v.y, s1);
    }
    red[sl][cp] = make_float2(s0, s1);
    __syncthreads();
    if (threadIdx.x < 32) {
        float a0 = 0.0f, a1 = 0.0f;
#pragma unroll
        for (int s = 0; s < 8; ++s) { a0 += red[s][threadIdx.x].x; a1 += red[s][threadIdx.x].y; }
        float2 iv = make_float2(rsqrtf(fmaxf(a0, 1e-12f)), rsqrtf(fmaxf(a1, 1e-12f)));
        sinv[threadIdx.x] = iv;
        *(float2*)(invp + b * CDIM + (cb << 6) + (threadIdx.x << 1)) = iv;
    }
    __syncthreads();
    const float2 iv = sinv[cp];

    for (int w = w0; w < w1; ++w) {
        const size_t idx = base + (size_t)w * CDIM;
        float2 v = *(const float2*)(in + idx);
        *(__half2*)(hp + idx) = __floats2half2_rn(v.x * iv.x, v.y * iv.y);
    }
}

// ======================= kernel 2: strips (j=512 row, w'=512 col); inits out =======================
__global__ void __launch_bounds__(512) strip_kernel(const float* __restrict__ x1,
                                                    const float* __restrict__ x2,
                                                    float* __restrict__ out) {
    __shared__ float p1[CDIM], p2[CDIM], acc[WDIM];
    const int b = blockIdx.x;
    const int tid = threadIdx.x;
    const int wid = tid >> 5, lane = tid & 31;

    {
        float iv = g_inv1[b * CDIM + tid] * g_inv2[b * CDIM + tid];
        p1[tid] = x1[((size_t)b * WDIM + 512) * CDIM + tid] * iv;  // x1n[512]·inv2
        p2[tid] = x2[((size_t)b * WDIM + 512) * CDIM + tid] * iv;  // x2n[512]·inv1
    }
    __syncthreads();

    // part 1: j = 512 fixed, all w':  out[(768-w') % 513] = <p1, x2[w',:]>  (covers every w once)
    for (int wp = wid; wp < WDIM; wp += 16) {
        const float4* row = (const float4*)(x2 + ((size_t)b * WDIM + wp) * CDIM);
        const float4* P   = (const float4*)p1;
        float s = 0.0f;
#pragma unroll
        for (int q = 0; q < 4; ++q) {
            float4 a  = row[lane + (q << 5)];
            float4 pv = P[lane + (q << 5)];
            s += a.x * pv.x + a.y * pv.y + a.z * pv.z + a.w * pv.w;
        }
        for (int o = 16; o; o >>= 1) s += __shfl_xor_sync(0xFFFFFFFFu, s, o);
        if (lane == 0) acc[(768 - wp) % WDIM] = s;
    }
    __syncthreads();

    // part 2: w' = 512 fixed, j in 0..511:  out[(j+257) % 513] += <p2, x1[j,:]>
    for (int j = wid; j < 512; j += 16) {
        const float4* row = (const float4*)(x1 + ((size_t)b * WDIM + j) * CDIM);
        const float4* P   = (const float4*)p2;
        float s = 0.0f;
#pragma unroll
        for (int q = 0; q < 4; ++q) {
            float4 a  = row[lane + (q << 5)];
            float4 pv = P[lane + (q << 5)];
            s += a.x * pv.x + a.y * pv.y + a.z * pv.z + a.w * pv.w;
        }
        for (int o = 16; o; o >>= 1) s += __shfl_xor_sync(0xFFFFFFFFu, s, o);
        if (lane == 0) acc[(j + 257) % WDIM] += s;
    }
    __syncthreads();

    for (int w = tid; w < WDIM; w += 512) out[(size_t)b * WDIM + w] = acc[w];
}

// ======================= kernel 3: fp16 mma.sync GEMM, K = 512 (single term) ==========
// CTA: 128(M=j) x 128(N=w') Gram tile; 8 chunks of 64 halves, 3-stage cp.async.
// 256 threads = 8 warps (4M x 2N), warp tile 32x64 (round-4/6 proven config).
#define NCHUNKS  8                     // 512 / 64
#define STAGE    32768                 // A 16KB + B 16KB (128 rows x 128B each)
#define NSTAGE   3
#define CPITCH   130
#define SMEM_GEMM (NSTAGE * STAGE)     // 98304 >= epilogue 128*130*4 = 66560

__global__ void __launch_bounds__(256, 2) gemm_kernel(float* __restrict__ out) {
    extern __shared__ char sm[];
    const uint32_t sb = smem_u32(sm);

    const int tid  = threadIdx.x;
    const int lane = tid & 31, warp = tid >> 5;
    const int wm = warp >> 1, wn = warp & 1;       // warp grid 4(M) x 2(N)
    const int l15 = lane & 15;

    const int b  = blockIdx.x >> 4;
    const int j0 = ((blockIdx.x >> 2) & 3) << 7;
    const int n0 = (blockIdx.x & 3) << 7;

    float acc[2][8][4];
#pragma unroll
    for (int mt = 0; mt < 2; ++mt)
#pragma unroll
        for (int nt = 0; nt < 8; ++nt)
#pragma unroll
            for (int i = 0; i < 4; ++i) acc[mt][nt][i] = 0.0f;

    // O(1)-register loader bases (swizzle is q-invariant: row steps by 32 per q)
    const int lr = tid >> 3, lc = tid & 7;
    const uint32_t dOff0 = (uint32_t)((lr << 7) + ((lc ^ (lr & 7)) << 4));
    const uint32_t sOff0 = (uint32_t)(lr * CDIM + (lc << 3));
    const __half* pA = g_h1 + ((size_t)(b * WDIM + j0)) * CDIM + sOff0;
    const __half* pB = g_h2 + ((size_t)(b * WDIM + n0)) * CDIM + sOff0;

    // per-lane ldmatrix address components (row base * 128B + swizzled 16B chunk)
    uint32_t offk[4];
#pragma unroll
    for (int ks = 0; ks < 4; ++ks)
        offk[ks] = (uint32_t)((((ks << 1) | (lane >> 4)) ^ (lane & 7)) << 4);
    uint32_t arow[2], brow[4];
#pragma unroll
    for (int mt = 0; mt < 2; ++mt) arow[mt] = (uint32_t)((wm * 32 + mt * 16 + l15) << 7);
#pragma unroll
    for (int ng = 0; ng < 4; ++ng) brow[ng] = (uint32_t)((wn * 64 + ng * 16 + l15) << 7);

    // async chunk loader: 64 halves of K (128B/row), XOR-swizzled 16B chunks
    auto load_chunk = [&](int k, int s) {
        const uint32_t c0 = k << 6;
        const uint32_t sA = sb + s * STAGE + dOff0;
        const uint32_t sB = sA + 16384;
#pragma unroll
        for (int q = 0; q < 4; ++q) CP_ASYNC16(sA + q * 4096, pA + c0 + q * (32 * CDIM));
#pragma unroll
        for (int q = 0; q < 4; ++q) CP_ASYNC16(sB + q * 4096, pB + c0 + q * (32 * CDIM));
        CP_COMMIT();
    };

    load_chunk(0, 0);
    load_chunk(1, 1);

    int st = 0, ls = 2;
    for (int k = 0; k < NCHUNKS; ++k) {
        if (k < NCHUNKS - 1) { CP_WAIT(1); } else { CP_WAIT(0); }
        __syncthreads();
        if (k + 2 < NCHUNKS) load_chunk(k + 2, ls);

        const uint32_t sA = sb + st * STAGE;
        const uint32_t sB = sA + 16384;
#pragma unroll
        for (int ks = 0; ks < 4; ++ks) {
            uint32_t a0[4], a1[4];
            ldsm_x4(a0, sA + arow[0] + offk[ks]);
            ldsm_x4(a1, sA + arow[1] + offk[ks]);
#pragma unroll
            for (int ng = 0; ng < 4; ++ng) {
                uint32_t q[4];
                ldsm_x4(q, sB + brow[ng] + offk[ks]);
                mma16816(acc[0][ng * 2],     a0[0], a0[1], a0[2], a0[3], q[0], q[2]);
                mma16816(acc[0][ng * 2 + 1], a0[0], a0[1], a0[2], a0[3], q[1], q[3]);
                mma16816(acc[1][ng * 2],     a1[0], a1[1], a1[2], a1[3], q[0], q[2]);
                mma16816(acc[1][ng * 2 + 1], a1[0], a1[1], a1[2], a1[3], q[1], q[3]);
            }
        }
        st = (st == NSTAGE - 1) ? 0 : st + 1;
        ls = (ls == NSTAGE - 1) ? 0 : ls + 1;
    }

    // --- epilogue: stage C in smem, fold diagonals, atomicAdd to global ---
    __syncthreads();
    float* C = (float*)sm;
    const int g = lane >> 2, t4 = lane & 3;
#pragma unroll
    for (int mt = 0; mt < 2; ++mt) {
        const int r0 = wm * 32 + mt * 16 + g;
#pragma unroll
        for (int nt = 0; nt < 8; ++nt) {
            const int c = wn * 64 + nt * 8 + 2 * t4;
            C[r0 * CPITCH + c]           = acc[mt][nt][0];
            C[r0 * CPITCH + c + 1]       = acc[mt][nt][1];
            C[(r0 + 8) * CPITCH + c]     = acc[mt][nt][2];
            C[(r0 + 8) * CPITCH + c + 1] = acc[mt][nt][3];
        }
    }
    __syncthreads();

    if (tid < 255) {
        const int d = tid - 127;                 // diag offset r - c
        float s = 0.0f;
#pragma unroll 4
        for (int r = 0; r < 128; ++r) {
            const int c = r - d;
            if (c >= 0 && c < 128) s += C[r * CPITCH + c];
        }
        const int widx = (j0 - n0 + d + 256 + 1026) % WDIM;
        atomicAdd(&out[(size_t)b * WDIM + widx], s);
    }
}

// ======================= launch =======================
extern "C" void kernel_launch(void* const* d_in, const int* in_sizes, int n_in,
                              void* d_out, int out_size) {
    const float* x1 = (const float*)d_in[0];
    const float* x2 = (const float*)d_in[1];
    float* out = (float*)d_out;

    cudaFuncSetAttribute(gemm_kernel, cudaFuncAttributeMaxDynamicSharedMemorySize, SMEM_GEMM);

    prep_kernel<<<dim3(BATCH, 2, 8), 256>>>(x1, x2);
    strip_kernel<<<BATCH, 512>>>(x1, x2, out);
    gemm_kernel<<<BATCH * 16, 256, SMEM_GEMM>>>(out);
}